// round 8
// baseline (speedup 1.0000x reference)
#include <cuda_runtime.h>

// DisplacementVectorsASU — gather + per-edge affine transform.
//
// Inputs: frac_coords f32 (100000,3) | edge_indices i32 (2,4M) |
//         symmops f32 (4M,4,4) | cell_translations f32 (4M,3)
// Output: f32 (4M,3)
//
// R8 (evidence-driven):
//  - float4 node table, 1 LDG.128/gather (R3). Default policy on LDG (R4).
//  - 2 edges/thread, gathers front-batched in registers (R5 > R6).
//  - Streams (symmops, ct) via cp.async.cg into smem: frees ~12 regs
//    (48 -> ~40 => 6 CTAs/SM) and keeps L1 capacity for the gather table.
//  - Issue order: idx LDGs -> all cp.asyncs -> gather LDGs -> wait+sync.
//  - NOT R7: TPB=256, 36KB smem, registers still carry the gathers.

#define NODE_CAP 131072
__device__ float4 g_frac4[NODE_CAP];

__global__ __launch_bounds__(512)
void pack_frac_kernel(const float* __restrict__ frac, int n)
{
    int i = blockIdx.x * blockDim.x + threadIdx.x;
    if (i < n) {
        float4 v;
        v.x = __ldg(frac + 3 * i + 0);
        v.y = __ldg(frac + 3 * i + 1);
        v.z = __ldg(frac + 3 * i + 2);
        v.w = 0.0f;
        g_frac4[i] = v;
    }
}

#define TPB 256
#define EPB 512   // 2 edges per thread

__device__ __forceinline__ unsigned smem_u32(const void* p)
{
    unsigned a;
    asm("{ .reg .u64 t; cvta.to.shared.u64 t, %1; cvt.u32.u64 %0, t; }"
        : "=r"(a) : "l"(p));
    return a;
}

__device__ __forceinline__ void cp16cg(unsigned dst, const void* src)
{
    asm volatile("cp.async.cg.shared.global [%0], [%1], 16;"
                 :: "r"(dst), "l"(src));
}

__global__ __launch_bounds__(TPB)
void displacement_kernel(const int*    __restrict__ ei,
                         const float4* __restrict__ sym,   // 4 float4/edge
                         const float4* __restrict__ ct4,
                         float4*       __restrict__ out4,
                         int M)
{
    __shared__ float4 s_sym[EPB * 3];   // 24KB, slot-major (48B/edge, conflict-free LDS.128)
    __shared__ float  s_ct [EPB * 3];   // 6KB
    __shared__ float  s_out[EPB * 3];   // 6KB

    const int tid       = threadIdx.x;
    const int blockBase = blockIdx.x * EPB;
    const unsigned a_sym = smem_u32(s_sym);
    const unsigned a_ct  = smem_u32(s_ct);

    const int e0 = blockBase + tid;
    const int e1 = e0 + TPB;
    const bool v0 = (e0 < M);
    const bool v1 = (e1 < M);

    // 1) index loads first — head of the longest dependent chain
    int i0a = 0, i0b = 0, i1a = 0, i1b = 0;
    if (v0) { i0a = __ldg(ei + e0); i0b = __ldg(ei + M + e0); }
    if (v1) { i1a = __ldg(ei + e1); i1b = __ldg(ei + M + e1); }

    // 2) stream copies (independent of indices) — fill the pipe now
    if (v0) {
        const float4* sb = sym + 4L * e0;
        const unsigned d = a_sym + tid * 48;
        cp16cg(d +  0, sb + 0);
        cp16cg(d + 16, sb + 1);
        cp16cg(d + 32, sb + 2);
    }
    if (v1) {
        const float4* sb = sym + 4L * e1;
        const unsigned d = a_sym + (tid + TPB) * 48;
        cp16cg(d +  0, sb + 0);
        cp16cg(d + 16, sb + 1);
        cp16cg(d + 32, sb + 2);
    }
    {
        const long f4base = (long)blockBase * 3 / 4;   // EPB*3 % 4 == 0
        #pragma unroll
        for (int i = tid; i < EPB * 3 / 4; i += TPB) {
            if ((f4base + i) * 4 < (long)M * 3)
                cp16cg(a_ct + i * 16, ct4 + f4base + i);
        }
    }
    asm volatile("cp.async.commit_group;" ::: "memory");

    // 3) gathers — register destinations, issue as soon as indices land
    float4 fin0 = {0,0,0,0}, fo0 = {0,0,0,0};
    float4 fin1 = {0,0,0,0}, fo1 = {0,0,0,0};
    if (v0) { fin0 = __ldg(g_frac4 + i0a); fo0 = __ldg(g_frac4 + i0b); }
    if (v1) { fin1 = __ldg(g_frac4 + i1a); fo1 = __ldg(g_frac4 + i1b); }

    asm volatile("cp.async.wait_group 0;" ::: "memory");
    __syncthreads();

    // 4) compute (smem sym/ct + register gathers)
    if (v0) {
        const float4 r0 = s_sym[3 * tid + 0];
        const float4 r1 = s_sym[3 * tid + 1];
        const float4 r2 = s_sym[3 * tid + 2];
        float t0 = fmaf(r0.x, fo0.x, fmaf(r0.y, fo0.y, fmaf(r0.z, fo0.z, r0.w)));
        float t1 = fmaf(r1.x, fo0.x, fmaf(r1.y, fo0.y, fmaf(r1.z, fo0.z, r1.w)));
        float t2 = fmaf(r2.x, fo0.x, fmaf(r2.y, fo0.y, fmaf(r2.z, fo0.z, r2.w)));
        s_out[3 * tid + 0] = fin0.x - (t0 - floorf(t0) + s_ct[3 * tid + 0]);
        s_out[3 * tid + 1] = fin0.y - (t1 - floorf(t1) + s_ct[3 * tid + 1]);
        s_out[3 * tid + 2] = fin0.z - (t2 - floorf(t2) + s_ct[3 * tid + 2]);
    }
    if (v1) {
        const int u = tid + TPB;
        const float4 r0 = s_sym[3 * u + 0];
        const float4 r1 = s_sym[3 * u + 1];
        const float4 r2 = s_sym[3 * u + 2];
        float t0 = fmaf(r0.x, fo1.x, fmaf(r0.y, fo1.y, fmaf(r0.z, fo1.z, r0.w)));
        float t1 = fmaf(r1.x, fo1.x, fmaf(r1.y, fo1.y, fmaf(r1.z, fo1.z, r1.w)));
        float t2 = fmaf(r2.x, fo1.x, fmaf(r2.y, fo1.y, fmaf(r2.z, fo1.z, r2.w)));
        s_out[3 * u + 0] = fin1.x - (t0 - floorf(t0) + s_ct[3 * u + 0]);
        s_out[3 * u + 1] = fin1.y - (t1 - floorf(t1) + s_ct[3 * u + 1]);
        s_out[3 * u + 2] = fin1.z - (t2 - floorf(t2) + s_ct[3 * u + 2]);
    }
    __syncthreads();

    // 5) coalesced float4 store of the output
    {
        const long f4base = (long)blockBase * 3 / 4;
        #pragma unroll
        for (int i = tid; i < EPB * 3 / 4; i += TPB) {
            long idx = f4base + i;
            if (idx * 4 < (long)M * 3)
                out4[idx] = ((const float4*)s_out)[i];
        }
    }
}

extern "C" void kernel_launch(void* const* d_in, const int* in_sizes, int n_in,
                              void* d_out, int out_size)
{
    const float*  frac = (const float*) d_in[0];
    const int*    ei   = (const int*)   d_in[1];
    const float4* sym  = (const float4*)d_in[2];
    const float4* ct4  = (const float4*)d_in[3];
    float4*       out4 = (float4*)      d_out;

    const int n = in_sizes[0] / 3;      // node count
    const int M = in_sizes[1] / 2;      // edge count

    pack_frac_kernel<<<(n + 511) / 512, 512>>>(frac, n);

    const int blocks = (M + EPB - 1) / EPB;
    displacement_kernel<<<blocks, TPB>>>(ei, sym, ct4, out4, M);
}

// round 9
// speedup vs baseline: 1.5336x; 1.5336x over previous
#include <cuda_runtime.h>

// DisplacementVectorsASU — gather + per-edge affine transform.
//
// Inputs: frac_coords f32 (100000,3) | edge_indices i32 (2,4M) |
//         symmops f32 (4M,4,4) | cell_translations f32 (4M,3)
// Output: f32 (4M,3)
//
// R9 (evidence ledger):
//  - float4 node table, 1 LDG.128/gather (R3 win)
//  - default cache policy (R4: hints +24us) ; NO cp.async (R7/R8: +30..60us)
//  - 2 edges/thread, gathers front-batched in registers (R5 best, 72.3us)
//  - NEW: symmops staged through smem with an IDENTITY-COALESCED block copy
//    (consecutive lanes -> consecutive float4 => 4 lines/instr) instead of
//    per-thread 64B-strided LDG (16 lines/instr). Cuts sym L1 wavefronts
//    ~3x; total L1 work ~ -25%. Row planes padded -> LDS conflict-free.

#define NODE_CAP 131072
__device__ float4 g_frac4[NODE_CAP];

__global__ __launch_bounds__(512)
void pack_frac_kernel(const float* __restrict__ frac, int n)
{
    int i = blockIdx.x * blockDim.x + threadIdx.x;
    if (i < n) {
        float4 v;
        v.x = __ldg(frac + 3 * i + 0);
        v.y = __ldg(frac + 3 * i + 1);
        v.z = __ldg(frac + 3 * i + 2);
        v.w = 0.0f;
        g_frac4[i] = v;
    }
}

#define TPB   256
#define EPB   512            // 2 edges per thread
#define PLANE (EPB + 1)      // float4 units; +1 pad rotates banks per plane

__global__ __launch_bounds__(TPB)
void displacement_kernel(const int*    __restrict__ ei,
                         const float4* __restrict__ sym4,  // 4 float4 / edge
                         const float4* __restrict__ ct4,
                         float4*       __restrict__ out4,
                         int M)
{
    __shared__ float4 s_sym[PLANE * 3];   // ~24.6KB: row planes 0..2
    __shared__ float  s_ct [EPB * 3];     // 6KB
    float* s_out = (float*)s_sym;         // alias, used after barrier

    const int tid       = threadIdx.x;
    const int blockBase = blockIdx.x * EPB;

    const int e0 = blockBase + tid;
    const int e1 = e0 + TPB;
    const bool v0 = (e0 < M);
    const bool v1 = (e1 < M);

    // 1) index loads first (head of the dependent chain)
    int i0a = 0, i0b = 0, i1a = 0, i1b = 0;
    if (v0) { i0a = __ldg(ei + e0); i0b = __ldg(ei + M + e0); }
    if (v1) { i1a = __ldg(ei + e1); i1b = __ldg(ei + M + e1); }

    // 2) identity-coalesced symmop copy into row planes (row 3 skipped).
    //    Global float4 g = blockBase*4 + i ; row = i&3 ; edge = i>>2.
    {
        const int gbase = blockBase * 4;          // <= 16M, fits int32
        const int gmax  = M * 4;
        #pragma unroll
        for (int k = 0; k < (EPB * 4) / TPB; k++) {
            int i    = tid + k * TPB;
            int row  = i & 3;                     // constant per thread
            int edge = i >> 2;
            int g    = gbase + i;
            if (row < 3 && g < gmax)
                s_sym[row * PLANE + edge] = __ldg(sym4 + g);
        }
    }

    // 3) coalesced ct copy
    {
        const int f4base = (blockBase / 4) * 3;   // blockBase*3/4
        const int f4max  = (3 * M) / 4;           // 3M divisible by 4 here
        #pragma unroll
        for (int k = 0; k < 2; k++) {
            int i = tid + k * TPB;
            if (i < (EPB * 3) / 4 && (f4base + i) < f4max)
                ((float4*)s_ct)[i] = __ldg(ct4 + f4base + i);
        }
    }

    // 4) gathers — register destinations, front-batched (R5 pattern)
    float4 fin0 = {0,0,0,0}, fo0 = {0,0,0,0};
    float4 fin1 = {0,0,0,0}, fo1 = {0,0,0,0};
    if (v0) { fin0 = __ldg(g_frac4 + i0a); fo0 = __ldg(g_frac4 + i0b); }
    if (v1) { fin1 = __ldg(g_frac4 + i1a); fo1 = __ldg(g_frac4 + i1b); }

    __syncthreads();

    // 5) compute into registers (LDS.128 per plane: conflict-free)
    float ra[3], rb[3];
    if (v0) {
        const float4 a0 = s_sym[0 * PLANE + tid];
        const float4 a1 = s_sym[1 * PLANE + tid];
        const float4 a2 = s_sym[2 * PLANE + tid];
        float t0 = fmaf(a0.x, fo0.x, fmaf(a0.y, fo0.y, fmaf(a0.z, fo0.z, a0.w)));
        float t1 = fmaf(a1.x, fo0.x, fmaf(a1.y, fo0.y, fmaf(a1.z, fo0.z, a1.w)));
        float t2 = fmaf(a2.x, fo0.x, fmaf(a2.y, fo0.y, fmaf(a2.z, fo0.z, a2.w)));
        ra[0] = fin0.x - (t0 - floorf(t0) + s_ct[3 * tid + 0]);
        ra[1] = fin0.y - (t1 - floorf(t1) + s_ct[3 * tid + 1]);
        ra[2] = fin0.z - (t2 - floorf(t2) + s_ct[3 * tid + 2]);
    }
    if (v1) {
        const int u = tid + TPB;
        const float4 b0 = s_sym[0 * PLANE + u];
        const float4 b1 = s_sym[1 * PLANE + u];
        const float4 b2 = s_sym[2 * PLANE + u];
        float t0 = fmaf(b0.x, fo1.x, fmaf(b0.y, fo1.y, fmaf(b0.z, fo1.z, b0.w)));
        float t1 = fmaf(b1.x, fo1.x, fmaf(b1.y, fo1.y, fmaf(b1.z, fo1.z, b1.w)));
        float t2 = fmaf(b2.x, fo1.x, fmaf(b2.y, fo1.y, fmaf(b2.z, fo1.z, b2.w)));
        rb[0] = fin1.x - (t0 - floorf(t0) + s_ct[3 * u + 0]);
        rb[1] = fin1.y - (t1 - floorf(t1) + s_ct[3 * u + 1]);
        rb[2] = fin1.z - (t2 - floorf(t2) + s_ct[3 * u + 2]);
    }
    __syncthreads();   // all sym reads complete before aliasing as s_out

    if (v0) {
        s_out[3 * tid + 0] = ra[0];
        s_out[3 * tid + 1] = ra[1];
        s_out[3 * tid + 2] = ra[2];
    }
    if (v1) {
        const int u = tid + TPB;
        s_out[3 * u + 0] = rb[0];
        s_out[3 * u + 1] = rb[1];
        s_out[3 * u + 2] = rb[2];
    }
    __syncthreads();

    // 6) coalesced float4 store of the output
    {
        const int f4base = (blockBase / 4) * 3;
        const int f4max  = (3 * M) / 4;
        #pragma unroll
        for (int k = 0; k < 2; k++) {
            int i = tid + k * TPB;
            if (i < (EPB * 3) / 4 && (f4base + i) < f4max)
                out4[f4base + i] = ((const float4*)s_out)[i];
        }
    }
}

extern "C" void kernel_launch(void* const* d_in, const int* in_sizes, int n_in,
                              void* d_out, int out_size)
{
    const float*  frac = (const float*) d_in[0];
    const int*    ei   = (const int*)   d_in[1];
    const float4* sym4 = (const float4*)d_in[2];
    const float4* ct4  = (const float4*)d_in[3];
    float4*       out4 = (float4*)      d_out;

    const int n = in_sizes[0] / 3;      // node count
    const int M = in_sizes[1] / 2;      // edge count

    pack_frac_kernel<<<(n + 511) / 512, 512>>>(frac, n);

    const int blocks = (M + EPB - 1) / EPB;
    displacement_kernel<<<blocks, TPB>>>(ei, sym4, ct4, out4, M);
}

// round 10
// speedup vs baseline: 1.7374x; 1.1329x over previous
#include <cuda_runtime.h>

// DisplacementVectorsASU — gather + per-edge affine transform.
//
// Inputs: frac_coords f32 (100000,3) | edge_indices i32 (2,4M) |
//         symmops f32 (4M,4,4) | cell_translations f32 (4M,3)
// Output: f32 (4M,3)
//
// R10 (evidence ledger):
//  - float4 node table, 1 LDG.128/gather (R3 win)
//  - default cache policy only (R4/R8: hints lose)
//  - NO cp.async, NO pre-compute barriers (R7/R8/R9: all lose)
//  - register front-batched gathers = the one lever that wins (R5)
//  - NEW: EPT=4 — 8 front-batched gathers/thread (2x R5's in-flight gather
//    count at the same 5 CTAs/SM), symmops consumed per-edge to fit the
//    51-reg cap from __launch_bounds__(256,5).

#define NODE_CAP 131072
__device__ float4 g_frac4[NODE_CAP];

__global__ __launch_bounds__(512)
void pack_frac_kernel(const float* __restrict__ frac, int n)
{
    int i = blockIdx.x * blockDim.x + threadIdx.x;
    if (i < n) {
        float4 v;
        v.x = __ldg(frac + 3 * i + 0);
        v.y = __ldg(frac + 3 * i + 1);
        v.z = __ldg(frac + 3 * i + 2);
        v.w = 0.0f;
        g_frac4[i] = v;
    }
}

#define TPB 256
#define EPT 4
#define EPB 1024   // TPB * EPT

__global__ __launch_bounds__(TPB, 5)
void displacement_kernel(const int*    __restrict__ ei,
                         const float4* __restrict__ sym,   // 4 float4 / edge
                         const float4* __restrict__ ct4,
                         float4*       __restrict__ out4,
                         int M)
{
    __shared__ float s_ct [EPB * 3];   // 12KB
    __shared__ float s_out[EPB * 3];   // 12KB

    const int tid       = threadIdx.x;
    const int blockBase = blockIdx.x * EPB;

    // ---- coalesced float4 load of cell_translations into smem ----
    {
        const long f4base = (long)blockBase * 3 / 4;   // EPB*3 % 4 == 0
        #pragma unroll
        for (int k = 0; k < (EPB * 3 / 4) / TPB; k++) {
            int i = tid + k * TPB;
            long idx = f4base + i;
            if (idx * 4 < (long)M * 3)
                ((float4*)s_ct)[i] = __ldg(ct4 + idx);
        }
    }
    // NOTE: no __syncthreads() needed before compute — each thread reads only
    // the s_ct entries it wrote? NOT true (strided layout). Barrier required,
    // but place it AFTER the gather issue below so gathers overlap it.

    // ---- front-batch indices + gathers (the long-latency divergent part) ----
    bool  val[EPT];
    float4 fin[EPT], fo[EPT];
    #pragma unroll
    for (int k = 0; k < EPT; k++) {
        const int e = blockBase + tid + k * TPB;
        val[k] = (e < M);
        int ia = 0, ib = 0;
        if (val[k]) { ia = __ldg(ei + e); ib = __ldg(ei + M + e); }
        fin[k] = make_float4(0.f, 0.f, 0.f, 0.f);
        fo[k]  = make_float4(0.f, 0.f, 0.f, 0.f);
        if (val[k]) { fin[k] = __ldg(g_frac4 + ia); fo[k] = __ldg(g_frac4 + ib); }
    }

    __syncthreads();   // s_ct ready; gathers already in flight

    // ---- per-edge: stream symmops, compute, stage result ----
    #pragma unroll
    for (int k = 0; k < EPT; k++) {
        if (val[k]) {
            const int lt = tid + k * TPB;
            const int e  = blockBase + lt;
            const long sb = 4L * e;
            const float4 r0 = __ldg(sym + sb + 0);
            const float4 r1 = __ldg(sym + sb + 1);
            const float4 r2 = __ldg(sym + sb + 2);
            const float4 o  = fo[k];
            float t0 = fmaf(r0.x, o.x, fmaf(r0.y, o.y, fmaf(r0.z, o.z, r0.w)));
            float t1 = fmaf(r1.x, o.x, fmaf(r1.y, o.y, fmaf(r1.z, o.z, r1.w)));
            float t2 = fmaf(r2.x, o.x, fmaf(r2.y, o.y, fmaf(r2.z, o.z, r2.w)));
            s_out[3 * lt + 0] = fin[k].x - (t0 - floorf(t0) + s_ct[3 * lt + 0]);
            s_out[3 * lt + 1] = fin[k].y - (t1 - floorf(t1) + s_ct[3 * lt + 1]);
            s_out[3 * lt + 2] = fin[k].z - (t2 - floorf(t2) + s_ct[3 * lt + 2]);
        }
    }
    __syncthreads();

    // ---- coalesced float4 store of the output ----
    {
        const long f4base = (long)blockBase * 3 / 4;
        #pragma unroll
        for (int k = 0; k < (EPB * 3 / 4) / TPB; k++) {
            int i = tid + k * TPB;
            long idx = f4base + i;
            if (idx * 4 < (long)M * 3)
                out4[idx] = ((const float4*)s_out)[i];
        }
    }
}

extern "C" void kernel_launch(void* const* d_in, const int* in_sizes, int n_in,
                              void* d_out, int out_size)
{
    const float*  frac = (const float*) d_in[0];
    const int*    ei   = (const int*)   d_in[1];
    const float4* sym  = (const float4*)d_in[2];
    const float4* ct4  = (const float4*)d_in[3];
    float4*       out4 = (float4*)      d_out;

    const int n = in_sizes[0] / 3;      // node count
    const int M = in_sizes[1] / 2;      // edge count

    pack_frac_kernel<<<(n + 511) / 512, 512>>>(frac, n);

    const int blocks = (M + EPB - 1) / EPB;
    displacement_kernel<<<blocks, TPB>>>(ei, sym, ct4, out4, M);
}

// round 11
// speedup vs baseline: 1.8496x; 1.0646x over previous
#include <cuda_runtime.h>

// DisplacementVectorsASU — gather + per-edge affine transform.
//
// Inputs: frac_coords f32 (100000,3) | edge_indices i32 (2,4M) |
//         symmops f32 (4M,4,4) | cell_translations f32 (4M,3)
// Output: f32 (4M,3)
//
// R11 = R5 (measured optimum: EPT=2, ALL loads register-front-batched,
// default cache policy, no cp.async, smem-staged ct/out) plus:
//  - s_ct/s_out aliased into one buffer (race-free: each thread reads then
//    overwrites only its own 6 slots between barriers) -> 6KB smem/CTA
//  - TPB=192 -> 7 CTAs/SM at 48 regs (42 warps vs 40)
//  - pack kernel via smem transpose: fully coalesced float4 in and out

#define NODE_CAP 131072
__device__ float4 g_frac4[NODE_CAP];

// Block of 256 threads packs 256 nodes: coalesced float4 reads of frac
// (768 floats = 192 float4), smem transpose, coalesced float4 table writes.
__global__ __launch_bounds__(256)
void pack_frac_kernel(const float4* __restrict__ frac4, int n)   // n % 4 == 0
{
    __shared__ float s_f[768];
    const int tid  = threadIdx.x;
    const int base = blockIdx.x * 256;          // first node of this block

    const int f4base = base * 3 / 4;            // base % 4 == 0
    const int f4tot  = (n * 3) / 4;
    if (tid < 192) {
        int idx = f4base + tid;
        if (idx < f4tot)
            ((float4*)s_f)[tid] = __ldg(frac4 + idx);
    }
    __syncthreads();

    const int node = base + tid;
    if (node < n) {
        float4 v;
        v.x = s_f[3 * tid + 0];
        v.y = s_f[3 * tid + 1];
        v.z = s_f[3 * tid + 2];
        v.w = 0.0f;
        g_frac4[node] = v;
    }
}

#define TPB 192
#define EPB 384   // 2 edges per thread

__global__ __launch_bounds__(TPB)
void displacement_kernel(const int*    __restrict__ ei,
                         const float4* __restrict__ sym,   // 4 float4 / edge
                         const float4* __restrict__ ct4,
                         float4*       __restrict__ out4,
                         int M)
{
    __shared__ float s_buf[EPB * 3];   // ct on entry, results on exit (aliased)

    const int tid       = threadIdx.x;
    const int blockBase = blockIdx.x * EPB;

    // ---- cooperative float4 load of cell_translations (coalesced) ----
    {
        const long f4base = (long)blockBase * 3 / 4;    // EPB*3 % 4 == 0
        #pragma unroll
        for (int k = 0; k < 2; k++) {
            int i = tid + k * TPB;
            if (i < EPB * 3 / 4) {
                long idx = f4base + i;
                if (idx * 4 < (long)M * 3)
                    ((float4*)s_buf)[i] = __ldg(ct4 + idx);
            }
        }
    }
    __syncthreads();

    const int e0 = blockBase + tid;
    const int e1 = e0 + TPB;
    const bool v0 = (e0 < M);
    const bool v1 = (e1 < M);

    // ---- front-batch EVERYTHING (R5 pattern): indices, gathers, symmops ----
    int i0a = 0, i0b = 0, i1a = 0, i1b = 0;
    if (v0) { i0a = __ldg(ei + e0); i0b = __ldg(ei + M + e0); }
    if (v1) { i1a = __ldg(ei + e1); i1b = __ldg(ei + M + e1); }

    float4 fin0 = {0,0,0,0}, fo0 = {0,0,0,0};
    float4 fin1 = {0,0,0,0}, fo1 = {0,0,0,0};
    if (v0) { fin0 = __ldg(g_frac4 + i0a); fo0 = __ldg(g_frac4 + i0b); }
    if (v1) { fin1 = __ldg(g_frac4 + i1a); fo1 = __ldg(g_frac4 + i1b); }

    float4 a0 = {0,0,0,0}, a1 = {0,0,0,0}, a2 = {0,0,0,0};
    float4 b0 = {0,0,0,0}, b1 = {0,0,0,0}, b2 = {0,0,0,0};
    if (v0) {
        const long sb = 4L * e0;
        a0 = __ldg(sym + sb + 0);
        a1 = __ldg(sym + sb + 1);
        a2 = __ldg(sym + sb + 2);
    }
    if (v1) {
        const long sb = 4L * e1;
        b0 = __ldg(sym + sb + 0);
        b1 = __ldg(sym + sb + 1);
        b2 = __ldg(sym + sb + 2);
    }

    // ---- compute; each thread reads then overwrites ONLY its own slots ----
    if (v0) {
        float t0 = fmaf(a0.x, fo0.x, fmaf(a0.y, fo0.y, fmaf(a0.z, fo0.z, a0.w)));
        float t1 = fmaf(a1.x, fo0.x, fmaf(a1.y, fo0.y, fmaf(a1.z, fo0.z, a1.w)));
        float t2 = fmaf(a2.x, fo0.x, fmaf(a2.y, fo0.y, fmaf(a2.z, fo0.z, a2.w)));
        const float c0 = s_buf[3 * tid + 0];
        const float c1 = s_buf[3 * tid + 1];
        const float c2 = s_buf[3 * tid + 2];
        s_buf[3 * tid + 0] = fin0.x - (t0 - floorf(t0) + c0);
        s_buf[3 * tid + 1] = fin0.y - (t1 - floorf(t1) + c1);
        s_buf[3 * tid + 2] = fin0.z - (t2 - floorf(t2) + c2);
    }
    if (v1) {
        const int u = tid + TPB;
        float t0 = fmaf(b0.x, fo1.x, fmaf(b0.y, fo1.y, fmaf(b0.z, fo1.z, b0.w)));
        float t1 = fmaf(b1.x, fo1.x, fmaf(b1.y, fo1.y, fmaf(b1.z, fo1.z, b1.w)));
        float t2 = fmaf(b2.x, fo1.x, fmaf(b2.y, fo1.y, fmaf(b2.z, fo1.z, b2.w)));
        const float c0 = s_buf[3 * u + 0];
        const float c1 = s_buf[3 * u + 1];
        const float c2 = s_buf[3 * u + 2];
        s_buf[3 * u + 0] = fin1.x - (t0 - floorf(t0) + c0);
        s_buf[3 * u + 1] = fin1.y - (t1 - floorf(t1) + c1);
        s_buf[3 * u + 2] = fin1.z - (t2 - floorf(t2) + c2);
    }
    __syncthreads();

    // ---- cooperative float4 store of the output (coalesced) ----
    {
        const long f4base = (long)blockBase * 3 / 4;
        #pragma unroll
        for (int k = 0; k < 2; k++) {
            int i = tid + k * TPB;
            if (i < EPB * 3 / 4) {
                long idx = f4base + i;
                if (idx * 4 < (long)M * 3)
                    out4[idx] = ((const float4*)s_buf)[i];
            }
        }
    }
}

extern "C" void kernel_launch(void* const* d_in, const int* in_sizes, int n_in,
                              void* d_out, int out_size)
{
    const float4* frac4 = (const float4*)d_in[0];
    const int*    ei    = (const int*)   d_in[1];
    const float4* sym   = (const float4*)d_in[2];
    const float4* ct4   = (const float4*)d_in[3];
    float4*       out4  = (float4*)      d_out;

    const int n = in_sizes[0] / 3;      // node count (100000, div by 4)
    const int M = in_sizes[1] / 2;      // edge count

    pack_frac_kernel<<<(n + 255) / 256, 256>>>(frac4, n);

    const int blocks = (M + EPB - 1) / EPB;
    displacement_kernel<<<blocks, TPB>>>(ei, sym, ct4, out4, M);
}

// round 12
// speedup vs baseline: 1.8528x; 1.0017x over previous
#include <cuda_runtime.h>

// DisplacementVectorsASU — gather + per-edge affine transform.
//
// Inputs: frac_coords f32 (100000,3) | edge_indices i32 (2,4M) |
//         symmops f32 (4M,4,4) | cell_translations f32 (4M,3)
// Output: f32 (4M,3)
//
// R12 = R11 main kernel (measured 69.6us: TPB=192, EPT=2, ALL loads
// register-front-batched, default cache policy, no cp.async, aliased
// 4.5KB ct/out smem buffer) + R3's pack kernel (measured 2.6us overhead,
// the cheapest of the three pack variants tried).
//
// Evidence ledger:
//  - float4 node table, 1 LDG.128/gather (R3 win)
//  - default cache policy only (R4/R8: hints lose badly)
//  - NO cp.async (R7/R8), NO pre-gather staging barriers (R9)
//  - full register front-batching at EPT=2 (R5 > R6, R10)
//  - small smem footprint -> bigger L1 carveout for gather table (R11 win)

#define NODE_CAP 131072
__device__ float4 g_frac4[NODE_CAP];

// R3 pack: one thread per node, 3 scalar loads + one STG.128. 256 TPB.
__global__ __launch_bounds__(256)
void pack_frac_kernel(const float* __restrict__ frac, int n)
{
    int i = blockIdx.x * blockDim.x + threadIdx.x;
    if (i < n) {
        float4 v;
        v.x = frac[3 * i + 0];
        v.y = frac[3 * i + 1];
        v.z = frac[3 * i + 2];
        v.w = 0.0f;
        g_frac4[i] = v;
    }
}

#define TPB 192
#define EPB 384   // 2 edges per thread

__global__ __launch_bounds__(TPB)
void displacement_kernel(const int*    __restrict__ ei,
                         const float4* __restrict__ sym,   // 4 float4 / edge
                         const float4* __restrict__ ct4,
                         float4*       __restrict__ out4,
                         int M)
{
    __shared__ float s_buf[EPB * 3];   // ct on entry, results on exit (aliased)

    const int tid       = threadIdx.x;
    const int blockBase = blockIdx.x * EPB;

    // ---- cooperative float4 load of cell_translations (coalesced) ----
    {
        const long f4base = (long)blockBase * 3 / 4;    // EPB*3 % 4 == 0
        #pragma unroll
        for (int k = 0; k < 2; k++) {
            int i = tid + k * TPB;
            if (i < EPB * 3 / 4) {
                long idx = f4base + i;
                if (idx * 4 < (long)M * 3)
                    ((float4*)s_buf)[i] = __ldg(ct4 + idx);
            }
        }
    }
    __syncthreads();

    const int e0 = blockBase + tid;
    const int e1 = e0 + TPB;
    const bool v0 = (e0 < M);
    const bool v1 = (e1 < M);

    // ---- front-batch EVERYTHING (R5 pattern): indices, gathers, symmops ----
    int i0a = 0, i0b = 0, i1a = 0, i1b = 0;
    if (v0) { i0a = __ldg(ei + e0); i0b = __ldg(ei + M + e0); }
    if (v1) { i1a = __ldg(ei + e1); i1b = __ldg(ei + M + e1); }

    float4 fin0 = {0,0,0,0}, fo0 = {0,0,0,0};
    float4 fin1 = {0,0,0,0}, fo1 = {0,0,0,0};
    if (v0) { fin0 = __ldg(g_frac4 + i0a); fo0 = __ldg(g_frac4 + i0b); }
    if (v1) { fin1 = __ldg(g_frac4 + i1a); fo1 = __ldg(g_frac4 + i1b); }

    float4 a0 = {0,0,0,0}, a1 = {0,0,0,0}, a2 = {0,0,0,0};
    float4 b0 = {0,0,0,0}, b1 = {0,0,0,0}, b2 = {0,0,0,0};
    if (v0) {
        const long sb = 4L * e0;
        a0 = __ldg(sym + sb + 0);
        a1 = __ldg(sym + sb + 1);
        a2 = __ldg(sym + sb + 2);
    }
    if (v1) {
        const long sb = 4L * e1;
        b0 = __ldg(sym + sb + 0);
        b1 = __ldg(sym + sb + 1);
        b2 = __ldg(sym + sb + 2);
    }

    // ---- compute; each thread reads then overwrites ONLY its own slots ----
    if (v0) {
        float t0 = fmaf(a0.x, fo0.x, fmaf(a0.y, fo0.y, fmaf(a0.z, fo0.z, a0.w)));
        float t1 = fmaf(a1.x, fo0.x, fmaf(a1.y, fo0.y, fmaf(a1.z, fo0.z, a1.w)));
        float t2 = fmaf(a2.x, fo0.x, fmaf(a2.y, fo0.y, fmaf(a2.z, fo0.z, a2.w)));
        const float c0 = s_buf[3 * tid + 0];
        const float c1 = s_buf[3 * tid + 1];
        const float c2 = s_buf[3 * tid + 2];
        s_buf[3 * tid + 0] = fin0.x - (t0 - floorf(t0) + c0);
        s_buf[3 * tid + 1] = fin0.y - (t1 - floorf(t1) + c1);
        s_buf[3 * tid + 2] = fin0.z - (t2 - floorf(t2) + c2);
    }
    if (v1) {
        const int u = tid + TPB;
        float t0 = fmaf(b0.x, fo1.x, fmaf(b0.y, fo1.y, fmaf(b0.z, fo1.z, b0.w)));
        float t1 = fmaf(b1.x, fo1.x, fmaf(b1.y, fo1.y, fmaf(b1.z, fo1.z, b1.w)));
        float t2 = fmaf(b2.x, fo1.x, fmaf(b2.y, fo1.y, fmaf(b2.z, fo1.z, b2.w)));
        const float c0 = s_buf[3 * u + 0];
        const float c1 = s_buf[3 * u + 1];
        const float c2 = s_buf[3 * u + 2];
        s_buf[3 * u + 0] = fin1.x - (t0 - floorf(t0) + c0);
        s_buf[3 * u + 1] = fin1.y - (t1 - floorf(t1) + c1);
        s_buf[3 * u + 2] = fin1.z - (t2 - floorf(t2) + c2);
    }
    __syncthreads();

    // ---- cooperative float4 store of the output (coalesced) ----
    {
        const long f4base = (long)blockBase * 3 / 4;
        #pragma unroll
        for (int k = 0; k < 2; k++) {
            int i = tid + k * TPB;
            if (i < EPB * 3 / 4) {
                long idx = f4base + i;
                if (idx * 4 < (long)M * 3)
                    out4[idx] = ((const float4*)s_buf)[i];
            }
        }
    }
}

extern "C" void kernel_launch(void* const* d_in, const int* in_sizes, int n_in,
                              void* d_out, int out_size)
{
    const float*  frac = (const float*) d_in[0];
    const int*    ei   = (const int*)   d_in[1];
    const float4* sym  = (const float4*)d_in[2];
    const float4* ct4  = (const float4*)d_in[3];
    float4*       out4 = (float4*)      d_out;

    const int n = in_sizes[0] / 3;      // node count
    const int M = in_sizes[1] / 2;      // edge count

    pack_frac_kernel<<<(n + 255) / 256, 256>>>(frac, n);

    const int blocks = (M + EPB - 1) / EPB;
    displacement_kernel<<<blocks, TPB>>>(ei, sym, ct4, out4, M);
}

// round 13
// speedup vs baseline: 1.8767x; 1.0129x over previous
#include <cuda_runtime.h>

// DisplacementVectorsASU — gather + per-edge affine transform.
//
// Inputs: frac_coords f32 (100000,3) | edge_indices i32 (2,4M) |
//         symmops f32 (4M,4,4) | cell_translations f32 (4M,3)
// Output: f32 (4M,3)
//
// R13 = R12 (main 69.5us measured) with ONE change: the ct-staging barrier
// moved AFTER all global loads are issued. R12 ordering was
//   ct->smem, BARRIER, idx, gathers, sym   (two serialized memory epochs)
// R13 ordering is
//   idx, sym, ct->smem, gathers, BARRIER   (one epoch; barrier wait overlaps
//                                           gather/sym latency)
//
// Evidence ledger:
//  - float4 node table, 1 LDG.128/gather (R3) ; default cache policy (R4/R8)
//  - NO cp.async (R7/R8) ; NO barrier ahead of gather issue (R9, this round)
//  - full register front-batching at EPT=2 (R5 > R6, R10)
//  - small smem footprint -> bigger L1 gather carveout (R11)

#define NODE_CAP 131072
__device__ float4 g_frac4[NODE_CAP];

__global__ __launch_bounds__(256)
void pack_frac_kernel(const float* __restrict__ frac, int n)
{
    int i = blockIdx.x * blockDim.x + threadIdx.x;
    if (i < n) {
        float4 v;
        v.x = frac[3 * i + 0];
        v.y = frac[3 * i + 1];
        v.z = frac[3 * i + 2];
        v.w = 0.0f;
        g_frac4[i] = v;
    }
}

#define TPB 192
#define EPB 384   // 2 edges per thread

__global__ __launch_bounds__(TPB)
void displacement_kernel(const int*    __restrict__ ei,
                         const float4* __restrict__ sym,   // 4 float4 / edge
                         const float4* __restrict__ ct4,
                         float4*       __restrict__ out4,
                         int M)
{
    __shared__ float s_buf[EPB * 3];   // ct on entry, results on exit (aliased)

    const int tid       = threadIdx.x;
    const int blockBase = blockIdx.x * EPB;

    const int e0 = blockBase + tid;
    const int e1 = e0 + TPB;
    const bool v0 = (e0 < M);
    const bool v1 = (e1 < M);

    // 1) index loads — head of the longest dependent chain, issue first
    int i0a = 0, i0b = 0, i1a = 0, i1b = 0;
    if (v0) { i0a = __ldg(ei + e0); i0b = __ldg(ei + M + e0); }
    if (v1) { i1a = __ldg(ei + e1); i1b = __ldg(ei + M + e1); }

    // 2) symmop rows (independent coalesced streams)
    float4 a0 = {0,0,0,0}, a1 = {0,0,0,0}, a2 = {0,0,0,0};
    float4 b0 = {0,0,0,0}, b1 = {0,0,0,0}, b2 = {0,0,0,0};
    if (v0) {
        const long sb = 4L * e0;
        a0 = __ldg(sym + sb + 0);
        a1 = __ldg(sym + sb + 1);
        a2 = __ldg(sym + sb + 2);
    }
    if (v1) {
        const long sb = 4L * e1;
        b0 = __ldg(sym + sb + 0);
        b1 = __ldg(sym + sb + 1);
        b2 = __ldg(sym + sb + 2);
    }

    // 3) ct -> smem (cooperative float4, coalesced); barrier comes later
    {
        const long f4base = (long)blockBase * 3 / 4;    // EPB*3 % 4 == 0
        #pragma unroll
        for (int k = 0; k < 2; k++) {
            int i = tid + k * TPB;
            if (i < EPB * 3 / 4) {
                long idx = f4base + i;
                if (idx * 4 < (long)M * 3)
                    ((float4*)s_buf)[i] = __ldg(ct4 + idx);
            }
        }
    }

    // 4) gathers — indices have had time to land; issue all four
    float4 fin0 = {0,0,0,0}, fo0 = {0,0,0,0};
    float4 fin1 = {0,0,0,0}, fo1 = {0,0,0,0};
    if (v0) { fin0 = __ldg(g_frac4 + i0a); fo0 = __ldg(g_frac4 + i0b); }
    if (v1) { fin1 = __ldg(g_frac4 + i1a); fo1 = __ldg(g_frac4 + i1b); }

    // 5) single barrier — wait overlaps gather/sym latency
    __syncthreads();

    // 6) compute; each thread reads then overwrites ONLY its own slots
    if (v0) {
        float t0 = fmaf(a0.x, fo0.x, fmaf(a0.y, fo0.y, fmaf(a0.z, fo0.z, a0.w)));
        float t1 = fmaf(a1.x, fo0.x, fmaf(a1.y, fo0.y, fmaf(a1.z, fo0.z, a1.w)));
        float t2 = fmaf(a2.x, fo0.x, fmaf(a2.y, fo0.y, fmaf(a2.z, fo0.z, a2.w)));
        const float c0 = s_buf[3 * tid + 0];
        const float c1 = s_buf[3 * tid + 1];
        const float c2 = s_buf[3 * tid + 2];
        s_buf[3 * tid + 0] = fin0.x - (t0 - floorf(t0) + c0);
        s_buf[3 * tid + 1] = fin0.y - (t1 - floorf(t1) + c1);
        s_buf[3 * tid + 2] = fin0.z - (t2 - floorf(t2) + c2);
    }
    if (v1) {
        const int u = tid + TPB;
        float t0 = fmaf(b0.x, fo1.x, fmaf(b0.y, fo1.y, fmaf(b0.z, fo1.z, b0.w)));
        float t1 = fmaf(b1.x, fo1.x, fmaf(b1.y, fo1.y, fmaf(b1.z, fo1.z, b1.w)));
        float t2 = fmaf(b2.x, fo1.x, fmaf(b2.y, fo1.y, fmaf(b2.z, fo1.z, b2.w)));
        const float c0 = s_buf[3 * u + 0];
        const float c1 = s_buf[3 * u + 1];
        const float c2 = s_buf[3 * u + 2];
        s_buf[3 * u + 0] = fin1.x - (t0 - floorf(t0) + c0);
        s_buf[3 * u + 1] = fin1.y - (t1 - floorf(t1) + c1);
        s_buf[3 * u + 2] = fin1.z - (t2 - floorf(t2) + c2);
    }
    __syncthreads();

    // 7) cooperative float4 store of the output (coalesced)
    {
        const long f4base = (long)blockBase * 3 / 4;
        #pragma unroll
        for (int k = 0; k < 2; k++) {
            int i = tid + k * TPB;
            if (i < EPB * 3 / 4) {
                long idx = f4base + i;
                if (idx * 4 < (long)M * 3)
                    out4[idx] = ((const float4*)s_buf)[i];
            }
        }
    }
}

extern "C" void kernel_launch(void* const* d_in, const int* in_sizes, int n_in,
                              void* d_out, int out_size)
{
    const float*  frac = (const float*) d_in[0];
    const int*    ei   = (const int*)   d_in[1];
    const float4* sym  = (const float4*)d_in[2];
    const float4* ct4  = (const float4*)d_in[3];
    float4*       out4 = (float4*)      d_out;

    const int n = in_sizes[0] / 3;      // node count
    const int M = in_sizes[1] / 2;      // edge count

    pack_frac_kernel<<<(n + 255) / 256, 256>>>(frac, n);

    const int blocks = (M + EPB - 1) / EPB;
    displacement_kernel<<<blocks, TPB>>>(ei, sym, ct4, out4, M);
}